// round 4
// baseline (speedup 1.0000x reference)
#include <cuda_runtime.h>
#include <math.h>

#define H 1024
#define F 128
#define F4 32
#define MAXS 8192
#define NPART 256
#define QPB 128          // k2ab blocks

// Scratch (rewritten every call => deterministic).
__device__ float g_partial[NPART * H];
__device__ float g_qp[QPB * F];
__device__ float g_w[2];          // 0.5 * sigmoid(score_k)
__device__ float g_v0[H];
__device__ float g_v1[H];
__device__ float g_r0[MAXS];
__device__ float g_r1[MAXS];
__device__ int   g_vdone;         // producer-done flag in kAB (reset by k4)
__device__ int   g_tick;          // last-block ticket in k2ab (reset by k4)

// ---------------------------------------------------------------------------
// temporal MLP -> mem[2*F] in shared (256 threads).
// ---------------------------------------------------------------------------
__device__ __forceinline__ void compute_mem(float* mem,
                                            const float* ts, const float* dg,
                                            const float* Wt1, const float* bt1,
                                            const float* Wt2, const float* bt2,
                                            int t) {
    int k = t >> 7, h = t & 127;
    float tk = ts[k];
    float acc = bt2[h];
    #pragma unroll
    for (int j = 0; j < F4; ++j) {
        float a = fmaxf(fmaf(tk, Wt1[j], bt1[j]), 0.f);
        acc = fmaf(a, Wt2[j * F + h], acc);
    }
    mem[t] = dg[k * F + h] + acc;
}

// ---------------------------------------------------------------------------
// kAB (branch A, fused): blocks 0..31 build v0/v1 (Wg^T mem + bg), signal;
// then all blocks (warp per row) compute r0[s]=v0.key[s], r1[s]=v1.key[s].
// ---------------------------------------------------------------------------
__global__ void kAB(const float4* __restrict__ key4,
                    const float* __restrict__ ts,  const float* __restrict__ dg,
                    const float* __restrict__ Wt1, const float* __restrict__ bt1,
                    const float* __restrict__ Wt2, const float* __restrict__ bt2,
                    const float* __restrict__ Wg,  const float* __restrict__ bg,
                    int S) {
    __shared__ float mem[2 * F];
    __shared__ float red0[256];
    __shared__ float red1[256];
    int t = threadIdx.x;

    if (blockIdx.x < 32) {
        compute_mem(mem, ts, dg, Wt1, bt1, Wt2, bt2, t);
        __syncthreads();
        int hcol = blockIdx.x * 32 + (t & 31);
        int fg = t >> 5;
        float a0 = 0.f, a1 = 0.f;
        #pragma unroll
        for (int f = fg * 16; f < fg * 16 + 16; ++f) {
            float w = Wg[(size_t)f * H + hcol];
            a0 = fmaf(mem[f], w, a0);
            a1 = fmaf(mem[F + f], w, a1);
        }
        red0[t] = a0; red1[t] = a1;
        __syncthreads();
        if (t < 128) { red0[t] += red0[t + 128]; red1[t] += red1[t + 128]; }
        __syncthreads();
        if (t < 64)  { red0[t] += red0[t + 64];  red1[t] += red1[t + 64]; }
        __syncthreads();
        if (t < 32) {
            float b = bg[hcol];
            g_v0[hcol] = red0[t] + red0[t + 32] + b;
            g_v1[hcol] = red1[t] + red1[t + 32] + b;
        }
        __threadfence();
        __syncthreads();
        if (t == 0) atomicAdd(&g_vdone, 1);
    }

    // Wait for all 32 producer slices.
    if (t == 0) {
        while (*(volatile int*)&g_vdone < 32) __nanosleep(64);
    }
    __syncthreads();
    __threadfence();

    // Dual matvec: warp per row.
    int warp = blockIdx.x * (blockDim.x >> 5) + (t >> 5);
    int lane = t & 31;
    if (warp >= S) return;
    const float4* k4 = key4 + (size_t)warp * (H / 4);
    const float4* v04 = (const float4*)g_v0;
    const float4* v14 = (const float4*)g_v1;
    float a0 = 0.f, a1 = 0.f;
    #pragma unroll
    for (int i = 0; i < (H / 4) / 32; ++i) {
        int idx = i * 32 + lane;
        float4 kv = __ldcs(k4 + idx);
        float4 x = __ldcg(v04 + idx);
        float4 y = __ldcg(v14 + idx);
        a0 = fmaf(kv.x, x.x, a0); a0 = fmaf(kv.y, x.y, a0);
        a0 = fmaf(kv.z, x.z, a0); a0 = fmaf(kv.w, x.w, a0);
        a1 = fmaf(kv.x, y.x, a1); a1 = fmaf(kv.y, y.y, a1);
        a1 = fmaf(kv.z, y.z, a1); a1 = fmaf(kv.w, y.w, a1);
    }
    #pragma unroll
    for (int off = 16; off; off >>= 1) {
        a0 += __shfl_xor_sync(0xFFFFFFFFu, a0, off);
        a1 += __shfl_xor_sync(0xFFFFFFFFu, a1, off);
    }
    if (lane == 0) { g_r0[warp] = a0; g_r1[warp] = a1; }
}

// ---------------------------------------------------------------------------
// K1 (branch B): partial column sums of query (S x H). 256 blocks.
// ---------------------------------------------------------------------------
__global__ void k1_qsum(const float4* __restrict__ q4, int S) {
    int b = blockIdx.x;
    int t = threadIdx.x;
    int rows = (S + gridDim.x - 1) / gridDim.x;
    int r0 = b * rows;
    int r1 = min(S, r0 + rows);
    float4 acc = make_float4(0.f, 0.f, 0.f, 0.f);
    for (int r = r0; r < r1; ++r) {
        float4 v = __ldcs(q4 + (size_t)r * (H / 4) + t);
        acc.x += v.x; acc.y += v.y; acc.z += v.z; acc.w += v.w;
    }
    ((float4*)g_partial)[b * (H / 4) + t] = acc;
}

// ---------------------------------------------------------------------------
// K2ab (branch B, fused): 128 blocks; block b owns 8 h-cols:
// reduce qmean slice, partial qpart; last block finishes scores -> g_w.
// ---------------------------------------------------------------------------
__global__ void k2ab(const float* __restrict__ ts,  const float* __restrict__ dg,
                     const float* __restrict__ Wt1, const float* __restrict__ bt1,
                     const float* __restrict__ Wt2, const float* __restrict__ bt2,
                     const float* __restrict__ Wa1, const float* __restrict__ ba1,
                     const float* __restrict__ Wa2, const float* __restrict__ ba2,
                     int S) {
    __shared__ float red[256];
    __shared__ float qm[8];
    __shared__ float mem[2 * F];
    __shared__ float qpart[F];
    __shared__ int islast;
    int b = blockIdx.x, t = threadIdx.x;
    int h0 = b * 8;

    // qmean slice: t = pl*8 + hl ; pl sums 8 of the 256 partials.
    {
        int hl = t & 7, pl = t >> 3;
        float s = 0.f;
        #pragma unroll
        for (int p = pl; p < NPART; p += 32)
            s += g_partial[p * H + h0 + hl];
        red[t] = s;
        __syncthreads();
        #pragma unroll
        for (int off = 128; off >= 8; off >>= 1) {
            if (t < off) red[t] += red[t + off];
            __syncthreads();
        }
        if (t < 8) qm[t] = red[t] / (float)S;
        __syncthreads();
    }

    // qpart partial: j = t&127; half handles 4 h each.
    {
        int j = t & 127, half = t >> 7;
        float acc = 0.f;
        #pragma unroll
        for (int hl = half * 4; hl < half * 4 + 4; ++hl)
            acc = fmaf(qm[hl], Wa1[(size_t)(F + h0 + hl) * F + j], acc);
        red[t] = acc;
        __syncthreads();
        if (t < 128) g_qp[b * F + t] = red[t] + red[t + 128];
    }

    __threadfence();
    __syncthreads();
    if (t == 0) {
        int old = atomicAdd(&g_tick, 1);
        islast = (old == QPB - 1);
    }
    __syncthreads();
    if (!islast) return;

    // Last block: finish qpart, mem, scores, weights.
    {
        int j = t & 127, half = t >> 7;
        float s = 0.f;
        for (int bb = half * (QPB / 2); bb < (half + 1) * (QPB / 2); ++bb)
            s += __ldcg(&g_qp[bb * F + j]);
        red[t] = s;
    }
    compute_mem(mem, ts, dg, Wt1, bt1, Wt2, bt2, t);
    __syncthreads();
    if (t < F) qpart[t] = red[t] + red[t + F];
    __syncthreads();

    {
        int k = t >> 7, j = t & 127;
        float acc = ba1[j] + qpart[j];
        #pragma unroll 8
        for (int f = 0; f < F; ++f)
            acc = fmaf(mem[k * F + f], Wa1[(size_t)f * F + j], acc);
        red[t] = tanhf(acc) * Wa2[j];
    }
    __syncthreads();
    for (int off = 64; off; off >>= 1) {
        if ((t & 127) < off) red[t] += red[t + off];
        __syncthreads();
    }
    if ((t & 127) == 0)
        g_w[t >> 7] = 0.5f / (1.f + expf(-(red[t] + ba2[0])));
}

// ---------------------------------------------------------------------------
// K4 (join): out[row][s] = w0*r0[s] + w1*r1[s]; resets counters for replay.
// ---------------------------------------------------------------------------
__global__ void k4_bcast(float* __restrict__ out, int S) {
    if (blockIdx.x == 0 && threadIdx.x == 0) { g_vdone = 0; g_tick = 0; }
    __shared__ float wsh[2];
    if (threadIdx.x < 2) wsh[threadIdx.x] = g_w[threadIdx.x];
    __syncthreads();
    float w0 = wsh[0], w1 = wsh[1];
    int row = blockIdx.x;
    const float4* r04 = (const float4*)g_r0;
    const float4* r14 = (const float4*)g_r1;
    float4* o4 = (float4*)(out + (size_t)row * S);
    int n4 = S >> 2;
    for (int c = threadIdx.x; c < n4; c += blockDim.x) {
        float4 a = __ldg(r04 + c);
        float4 b = __ldg(r14 + c);
        float4 v;
        v.x = fmaf(w0, a.x, w1 * b.x);
        v.y = fmaf(w0, a.y, w1 * b.y);
        v.z = fmaf(w0, a.z, w1 * b.z);
        v.w = fmaf(w0, a.w, w1 * b.w);
        __stcs(o4 + c, v);
    }
}

// ---------------------------------------------------------------------------
extern "C" void kernel_launch(void* const* d_in, const int* in_sizes, int n_in,
                              void* d_out, int out_size) {
    const float* query = (const float*)d_in[0];
    const float* key   = (const float*)d_in[1];
    const float* dg    = (const float*)d_in[2];
    const float* ts    = (const float*)d_in[3];
    const float* Wt1   = (const float*)d_in[4];
    const float* bt1   = (const float*)d_in[5];
    const float* Wt2   = (const float*)d_in[6];
    const float* bt2   = (const float*)d_in[7];
    const float* Wa1   = (const float*)d_in[8];
    const float* ba1   = (const float*)d_in[9];
    const float* Wa2   = (const float*)d_in[10];
    const float* ba2   = (const float*)d_in[11];
    const float* Wg    = (const float*)d_in[12];
    const float* bg    = (const float*)d_in[13];

    int S = in_sizes[1] / H;

    static cudaStream_t s2 = nullptr;
    static cudaEvent_t evFork = nullptr, evJoin = nullptr;
    if (!s2) {
        cudaStreamCreateWithFlags(&s2, cudaStreamNonBlocking);
        cudaEventCreateWithFlags(&evFork, cudaEventDisableTiming);
        cudaEventCreateWithFlags(&evJoin, cudaEventDisableTiming);
    }

    cudaEventRecord(evFork, 0);
    cudaStreamWaitEvent(s2, evFork, 0);

    // Branch A: fused v-build + dual key matvec.
    kAB<<<(S + 7) / 8, 256, 0, s2>>>((const float4*)key, ts, dg,
                                     Wt1, bt1, Wt2, bt2, Wg, bg, S);
    cudaEventRecord(evJoin, s2);

    // Branch B: query-side weights.
    k1_qsum<<<NPART, 256>>>((const float4*)query, S);
    k2ab<<<QPB, 256>>>(ts, dg, Wt1, bt1, Wt2, bt2, Wa1, ba1, Wa2, ba2, S);

    // Join and broadcast.
    cudaStreamWaitEvent(0, evJoin, 0);
    k4_bcast<<<S, 256>>>((float*)d_out, S);
}

// round 5
// speedup vs baseline: 1.0667x; 1.0667x over previous
#include <cuda_runtime.h>
#include <math.h>

#define H 1024
#define F 128
#define F4 32
#define MAXS 8192
#define G 592            // 148 SMs x 4 blocks — all-resident by construction
#define CBLK 128         // blocks doing the qpart stage

// Scratch (rewritten every call => deterministic).
__device__ float g_partial[G * H];
__device__ float g_qp[CBLK * F];
__device__ float g_w[2];          // 0.5 * sigmoid(score_k)
__device__ float g_v0[H];
__device__ float g_v1[H];
__device__ float g_r0[MAXS];
__device__ float g_r1[MAXS];
__device__ int   g_flagA;         // v0/v1 producer count (32)
__device__ int   g_flagB;         // query colsum count (G)
__device__ int   g_flagC;         // qpart ticket (CBLK)

// ---------------------------------------------------------------------------
// temporal MLP -> mem[2*F] in shared (256 threads).
// ---------------------------------------------------------------------------
__device__ __forceinline__ void compute_mem(float* mem,
                                            const float* ts, const float* dg,
                                            const float* Wt1, const float* bt1,
                                            const float* Wt2, const float* bt2,
                                            int t) {
    int k = t >> 7, h = t & 127;
    float tk = ts[k];
    float acc = bt2[h];
    #pragma unroll
    for (int j = 0; j < F4; ++j) {
        float a = fmaxf(fmaf(tk, Wt1[j], bt1[j]), 0.f);
        acc = fmaf(a, Wt2[j * F + h], acc);
    }
    mem[t] = dg[k * F + h] + acc;
}

// ---------------------------------------------------------------------------
// kPre: everything except the broadcast, in ONE all-resident launch.
// ---------------------------------------------------------------------------
__global__ void __launch_bounds__(256, 4)
kPre(const float4* __restrict__ q4, const float4* __restrict__ key4,
     const float* __restrict__ ts,  const float* __restrict__ dg,
     const float* __restrict__ Wt1, const float* __restrict__ bt1,
     const float* __restrict__ Wt2, const float* __restrict__ bt2,
     const float* __restrict__ Wa1, const float* __restrict__ ba1,
     const float* __restrict__ Wa2, const float* __restrict__ ba2,
     const float* __restrict__ Wg,  const float* __restrict__ bg,
     int S) {
    __shared__ float s0[256];
    __shared__ float s1[256];
    __shared__ float mem[2 * F];
    __shared__ float qm[8];
    __shared__ float qpart[F];
    __shared__ int slast;

    int t = threadIdx.x, b = blockIdx.x;

    // ---- A: blocks 0..31 produce v0/v1 h-slices (Wg^T mem + bg) ----
    if (b < 32) {
        compute_mem(mem, ts, dg, Wt1, bt1, Wt2, bt2, t);
        __syncthreads();
        int hcol = b * 32 + (t & 31);
        int fg = t >> 5;
        float a0 = 0.f, a1 = 0.f;
        #pragma unroll
        for (int f = fg * 16; f < fg * 16 + 16; ++f) {
            float w = Wg[(size_t)f * H + hcol];
            a0 = fmaf(mem[f], w, a0);
            a1 = fmaf(mem[F + f], w, a1);
        }
        s0[t] = a0; s1[t] = a1;
        __syncthreads();
        if (t < 128) { s0[t] += s0[t + 128]; s1[t] += s1[t + 128]; }
        __syncthreads();
        if (t < 64)  { s0[t] += s0[t + 64];  s1[t] += s1[t + 64]; }
        __syncthreads();
        if (t < 32) {
            float bb = bg[hcol];
            g_v0[hcol] = s0[t] + s0[t + 32] + bb;
            g_v1[hcol] = s1[t] + s1[t + 32] + bb;
        }
        __threadfence();
        __syncthreads();
        if (t == 0) atomicAdd(&g_flagA, 1);
        __syncthreads();
    }

    // ---- B: query column partial sums (all blocks) ----
    {
        int rpb = (S + G - 1) / G;
        int r0 = b * rpb;
        int r1 = min(S, r0 + rpb);
        float4 acc = make_float4(0.f, 0.f, 0.f, 0.f);
        for (int r = r0; r < r1; ++r) {
            float4 v = __ldcs(q4 + (size_t)r * (H / 4) + t);
            acc.x += v.x; acc.y += v.y; acc.z += v.z; acc.w += v.w;
        }
        ((float4*)g_partial)[b * (H / 4) + t] = acc;
        __threadfence();
        __syncthreads();
        if (t == 0) atomicAdd(&g_flagB, 1);
    }

    // ---- C (+D): blocks 0..127 finish qmean -> qpart -> scores -> g_w ----
    if (b < CBLK) {
        if (t == 0) {
            while (*(volatile int*)&g_flagB < G) __nanosleep(64);
        }
        __syncthreads();
        __threadfence();

        int h0 = b * 8;
        // qmean slice: t = pl*8 + hl ; pl strides 32 over G partials
        {
            int hl = t & 7, pl = t >> 3;
            float s = 0.f;
            for (int p = pl; p < G; p += 32)
                s += g_partial[p * H + h0 + hl];
            s0[t] = s;
            __syncthreads();
            #pragma unroll
            for (int off = 128; off >= 8; off >>= 1) {
                if (t < off) s0[t] += s0[t + off];
                __syncthreads();
            }
            if (t < 8) qm[t] = s0[t] / (float)S;
            __syncthreads();
        }
        // qpart partial
        {
            int j = t & 127, half = t >> 7;
            float acc = 0.f;
            #pragma unroll
            for (int hl = half * 4; hl < half * 4 + 4; ++hl)
                acc = fmaf(qm[hl], Wa1[(size_t)(F + h0 + hl) * F + j], acc);
            s0[t] = acc;
            __syncthreads();
            if (t < 128) g_qp[b * F + t] = s0[t] + s0[t + 128];
        }
        __threadfence();
        __syncthreads();
        if (t == 0) slast = (atomicAdd(&g_flagC, 1) == CBLK - 1);
        __syncthreads();

        if (slast) {
            __threadfence();
            // finish qpart over CBLK slices
            {
                int j = t & 127, half = t >> 7;
                float s = 0.f;
                for (int bb = half * (CBLK / 2); bb < (half + 1) * (CBLK / 2); ++bb)
                    s += g_qp[bb * F + j];
                s0[t] = s;
            }
            compute_mem(mem, ts, dg, Wt1, bt1, Wt2, bt2, t);
            __syncthreads();
            if (t < F) qpart[t] = s0[t] + s0[t + F];
            __syncthreads();
            // scores
            {
                int k = t >> 7, j = t & 127;
                float acc = ba1[j] + qpart[j];
                #pragma unroll 8
                for (int f = 0; f < F; ++f)
                    acc = fmaf(mem[k * F + f], Wa1[(size_t)f * F + j], acc);
                s0[t] = tanhf(acc) * Wa2[j];
            }
            __syncthreads();
            for (int off = 64; off; off >>= 1) {
                if ((t & 127) < off) s0[t] += s0[t + off];
                __syncthreads();
            }
            if ((t & 127) == 0)
                g_w[t >> 7] = 0.5f / (1.f + expf(-(s0[t] + ba2[0])));
        }
    }

    // ---- E: dual key matvec (needs v0/v1 only) ----
    if (t == 0) {
        while (*(volatile int*)&g_flagA < 32) __nanosleep(64);
    }
    __syncthreads();
    __threadfence();

    int gwarp = b * 8 + (t >> 5);
    int lane = t & 31;
    const int totW = G * 8;
    const float4* v04 = (const float4*)g_v0;
    const float4* v14 = (const float4*)g_v1;
    for (int row = gwarp; row < S; row += totW) {
        const float4* k4 = key4 + (size_t)row * (H / 4);
        float a0 = 0.f, a1 = 0.f;
        #pragma unroll
        for (int i = 0; i < (H / 4) / 32; ++i) {
            int idx = i * 32 + lane;
            float4 kv = __ldcs(k4 + idx);
            float4 x = __ldg(v04 + idx);
            float4 y = __ldg(v14 + idx);
            a0 = fmaf(kv.x, x.x, a0); a0 = fmaf(kv.y, x.y, a0);
            a0 = fmaf(kv.z, x.z, a0); a0 = fmaf(kv.w, x.w, a0);
            a1 = fmaf(kv.x, y.x, a1); a1 = fmaf(kv.y, y.y, a1);
            a1 = fmaf(kv.z, y.z, a1); a1 = fmaf(kv.w, y.w, a1);
        }
        #pragma unroll
        for (int off = 16; off; off >>= 1) {
            a0 += __shfl_xor_sync(0xFFFFFFFFu, a0, off);
            a1 += __shfl_xor_sync(0xFFFFFFFFu, a1, off);
        }
        if (lane == 0) { g_r0[row] = a0; g_r1[row] = a1; }
    }
}

// ---------------------------------------------------------------------------
// K4: out[row][s] = w0*r0[s] + w1*r1[s]; resets flags for graph replay.
// ---------------------------------------------------------------------------
__global__ void k4_bcast(float* __restrict__ out, int S) {
    if (blockIdx.x == 0 && threadIdx.x == 0) {
        g_flagA = 0; g_flagB = 0; g_flagC = 0;
    }
    __shared__ float wsh[2];
    if (threadIdx.x < 2) wsh[threadIdx.x] = g_w[threadIdx.x];
    __syncthreads();
    float w0 = wsh[0], w1 = wsh[1];
    int row = blockIdx.x;
    const float4* r04 = (const float4*)g_r0;
    const float4* r14 = (const float4*)g_r1;
    float4* o4 = (float4*)(out + (size_t)row * S);
    int n4 = S >> 2;
    for (int c = threadIdx.x; c < n4; c += blockDim.x) {
        float4 a = __ldg(r04 + c);
        float4 b = __ldg(r14 + c);
        float4 v;
        v.x = fmaf(w0, a.x, w1 * b.x);
        v.y = fmaf(w0, a.y, w1 * b.y);
        v.z = fmaf(w0, a.z, w1 * b.z);
        v.w = fmaf(w0, a.w, w1 * b.w);
        __stcs(o4 + c, v);
    }
}

// ---------------------------------------------------------------------------
extern "C" void kernel_launch(void* const* d_in, const int* in_sizes, int n_in,
                              void* d_out, int out_size) {
    const float* query = (const float*)d_in[0];
    const float* key   = (const float*)d_in[1];
    const float* dg    = (const float*)d_in[2];
    const float* ts    = (const float*)d_in[3];
    const float* Wt1   = (const float*)d_in[4];
    const float* bt1   = (const float*)d_in[5];
    const float* Wt2   = (const float*)d_in[6];
    const float* bt2   = (const float*)d_in[7];
    const float* Wa1   = (const float*)d_in[8];
    const float* ba1   = (const float*)d_in[9];
    const float* Wa2   = (const float*)d_in[10];
    const float* ba2   = (const float*)d_in[11];
    const float* Wg    = (const float*)d_in[12];
    const float* bg    = (const float*)d_in[13];

    int S = in_sizes[1] / H;

    kPre<<<G, 256>>>((const float4*)query, (const float4*)key,
                     ts, dg, Wt1, bt1, Wt2, bt2,
                     Wa1, ba1, Wa2, ba2, Wg, bg, S);
    k4_bcast<<<S, 256>>>((float*)d_out, S);
}

// round 6
// speedup vs baseline: 1.2238x; 1.1473x over previous
#include <cuda_runtime.h>
#include <math.h>

#define H 1024
#define F 128
#define F4 32
#define MAXS 8192
#define G 592            // 148 SMs x 4 blocks — all-resident by construction
#define ABLK 32          // blocks doing phase A
#define CBLK 128         // blocks doing the qpart stage
#define BCNT (G - ABLK)  // blocks doing query colsum
#define CH 8             // rows per dynamic grab (one per warp)

// Scratch (rewritten every call => deterministic).
__device__ float g_partial[G * H];
__device__ float g_qp[CBLK * F];
__device__ float g_w[2];
__device__ float g_v0[H];
__device__ float g_v1[H];
__device__ float g_r0[MAXS];
__device__ float g_r1[MAXS];
__device__ int   g_flagA;
__device__ int   g_flagB;
__device__ int   g_flagC;
__device__ int   g_rowctr;

// ---------------------------------------------------------------------------
__device__ __forceinline__ void compute_mem(float* mem,
                                            const float* ts, const float* dg,
                                            const float* Wt1, const float* bt1,
                                            const float* Wt2, const float* bt2,
                                            int t) {
    int k = t >> 7, h = t & 127;
    float tk = ts[k];
    float acc = bt2[h];
    #pragma unroll
    for (int j = 0; j < F4; ++j) {
        float a = fmaxf(fmaf(tk, Wt1[j], bt1[j]), 0.f);
        acc = fmaf(a, Wt2[j * F + h], acc);
    }
    mem[t] = dg[k * F + h] + acc;
}

// ---------------------------------------------------------------------------
// C-stage: block b (<CBLK) reduces its 8-h qmean slice and qpart partial;
// last ticket block finishes scores -> g_w.
// ---------------------------------------------------------------------------
__device__ void do_stage_C(int b, int t, float* s0, float* mem, float* qm,
                           float* qpart, int* slast,
                           const float* ts,  const float* dg,
                           const float* Wt1, const float* bt1,
                           const float* Wt2, const float* bt2,
                           const float* Wa1, const float* ba1,
                           const float* Wa2, const float* ba2, int S) {
    __threadfence();
    int h0 = b * 8;
    {
        int hl = t & 7, pl = t >> 3;
        float s = 0.f;
        for (int p = ABLK + pl; p < G; p += 32)   // only blocks >=ABLK wrote partials
            s += g_partial[p * H + h0 + hl];
        s0[t] = s;
        __syncthreads();
        #pragma unroll
        for (int off = 128; off >= 8; off >>= 1) {
            if (t < off) s0[t] += s0[t + off];
            __syncthreads();
        }
        if (t < 8) qm[t] = s0[t] / (float)S;
        __syncthreads();
    }
    {
        int j = t & 127, half = t >> 7;
        float acc = 0.f;
        #pragma unroll
        for (int hl = half * 4; hl < half * 4 + 4; ++hl)
            acc = fmaf(qm[hl], Wa1[(size_t)(F + h0 + hl) * F + j], acc);
        s0[t] = acc;
        __syncthreads();
        if (t < 128) g_qp[b * F + t] = s0[t] + s0[t + 128];
    }
    __threadfence();
    __syncthreads();
    if (t == 0) *slast = (atomicAdd(&g_flagC, 1) == CBLK - 1);
    __syncthreads();
    if (!*slast) return;

    __threadfence();
    {
        int j = t & 127, half = t >> 7;
        float s = 0.f;
        for (int bb = half * (CBLK / 2); bb < (half + 1) * (CBLK / 2); ++bb)
            s += g_qp[bb * F + j];
        s0[t] = s;
    }
    compute_mem(mem, ts, dg, Wt1, bt1, Wt2, bt2, t);
    __syncthreads();
    if (t < F) qpart[t] = s0[t] + s0[t + F];
    __syncthreads();
    {
        int k = t >> 7, j = t & 127;
        float acc = ba1[j] + qpart[j];
        #pragma unroll 8
        for (int f = 0; f < F; ++f)
            acc = fmaf(mem[k * F + f], Wa1[(size_t)f * F + j], acc);
        s0[t] = tanhf(acc) * Wa2[j];
    }
    __syncthreads();
    for (int off = 64; off; off >>= 1) {
        if ((t & 127) < off) s0[t] += s0[t + off];
        __syncthreads();
    }
    if ((t & 127) == 0)
        g_w[t >> 7] = 0.5f / (1.f + expf(-(s0[t] + ba2[0])));
}

// ---------------------------------------------------------------------------
__global__ void __launch_bounds__(256, 4)
kPre(const float4* __restrict__ q4, const float4* __restrict__ key4,
     const float* __restrict__ ts,  const float* __restrict__ dg,
     const float* __restrict__ Wt1, const float* __restrict__ bt1,
     const float* __restrict__ Wt2, const float* __restrict__ bt2,
     const float* __restrict__ Wa1, const float* __restrict__ ba1,
     const float* __restrict__ Wa2, const float* __restrict__ ba2,
     const float* __restrict__ Wg,  const float* __restrict__ bg,
     int S) {
    __shared__ float s0[256];
    __shared__ float s1[256];
    __shared__ float mem[2 * F];
    __shared__ float qm[8];
    __shared__ float qpart[F];
    __shared__ int slast;
    __shared__ int sh_row;
    __shared__ int sh_ready;

    int t = threadIdx.x, b = blockIdx.x;

    if (b < ABLK) {
        // ---- A: v0/v1 h-slices (Wg^T mem + bg); skip B ----
        compute_mem(mem, ts, dg, Wt1, bt1, Wt2, bt2, t);
        __syncthreads();
        int hcol = b * 32 + (t & 31);
        int fg = t >> 5;
        float a0 = 0.f, a1 = 0.f;
        #pragma unroll
        for (int f = fg * 16; f < fg * 16 + 16; ++f) {
            float w = Wg[(size_t)f * H + hcol];
            a0 = fmaf(mem[f], w, a0);
            a1 = fmaf(mem[F + f], w, a1);
        }
        s0[t] = a0; s1[t] = a1;
        __syncthreads();
        if (t < 128) { s0[t] += s0[t + 128]; s1[t] += s1[t + 128]; }
        __syncthreads();
        if (t < 64)  { s0[t] += s0[t + 64];  s1[t] += s1[t + 64]; }
        __syncthreads();
        if (t < 32) {
            float bb = bg[hcol];
            g_v0[hcol] = s0[t] + s0[t + 32] + bb;
            g_v1[hcol] = s1[t] + s1[t + 32] + bb;
        }
        __threadfence();
        __syncthreads();
        if (t == 0) atomicAdd(&g_flagA, 1);
        __syncthreads();
    } else {
        // ---- B: query column partial sums over blocks ABLK..G-1 ----
        int bb = b - ABLK;
        int rpb = (S + BCNT - 1) / BCNT;
        int r0 = bb * rpb;
        int r1 = min(S, r0 + rpb);
        float4 acc = make_float4(0.f, 0.f, 0.f, 0.f);
        for (int r = r0; r < r1; ++r) {
            float4 v = __ldcs(q4 + (size_t)r * (H / 4) + t);
            acc.x += v.x; acc.y += v.y; acc.z += v.z; acc.w += v.w;
        }
        ((float4*)g_partial)[b * (H / 4) + t] = acc;
        __threadfence();
        __syncthreads();
        if (t == 0) atomicAdd(&g_flagB, 1);
        __syncthreads();
    }

    // ---- wait for v0/v1 (producers finish early) ----
    if (t == 0) {
        while (*(volatile int*)&g_flagA < ABLK) __nanosleep(64);
    }
    __syncthreads();
    __threadfence();

    // ---- E: dynamic dual key matvec, with C-stage poll-interleave ----
    bool needC = (b < CBLK);
    int lane = t & 31, wid = t >> 5;
    const float4* v04 = (const float4*)g_v0;
    const float4* v14 = (const float4*)g_v1;

    for (;;) {
        if (needC) {
            if (t == 0) sh_ready = (*(volatile int*)&g_flagB >= BCNT);
            __syncthreads();
            if (sh_ready) {
                do_stage_C(b, t, s0, mem, qm, qpart, &slast,
                           ts, dg, Wt1, bt1, Wt2, bt2, Wa1, ba1, Wa2, ba2, S);
                needC = false;
                __syncthreads();
            }
        }
        if (t == 0) sh_row = atomicAdd(&g_rowctr, CH);
        __syncthreads();
        int row0 = sh_row;
        if (row0 >= S) break;
        int row = row0 + wid;
        if (row < S) {
            const float4* k4p = key4 + (size_t)row * (H / 4);
            float a0 = 0.f, a1 = 0.f;
            #pragma unroll
            for (int i = 0; i < (H / 4) / 32; ++i) {
                int idx = i * 32 + lane;
                float4 kv = __ldcs(k4p + idx);
                float4 x = __ldg(v04 + idx);
                float4 y = __ldg(v14 + idx);
                a0 = fmaf(kv.x, x.x, a0); a0 = fmaf(kv.y, x.y, a0);
                a0 = fmaf(kv.z, x.z, a0); a0 = fmaf(kv.w, x.w, a0);
                a1 = fmaf(kv.x, y.x, a1); a1 = fmaf(kv.y, y.y, a1);
                a1 = fmaf(kv.z, y.z, a1); a1 = fmaf(kv.w, y.w, a1);
            }
            #pragma unroll
            for (int off = 16; off; off >>= 1) {
                a0 += __shfl_xor_sync(0xFFFFFFFFu, a0, off);
                a1 += __shfl_xor_sync(0xFFFFFFFFu, a1, off);
            }
            if (lane == 0) { g_r0[row] = a0; g_r1[row] = a1; }
        }
        __syncthreads();
    }

    // If C never became ready during the row loop, finish it now.
    if (needC) {
        if (t == 0) {
            while (*(volatile int*)&g_flagB < BCNT) __nanosleep(64);
        }
        __syncthreads();
        do_stage_C(b, t, s0, mem, qm, qpart, &slast,
                   ts, dg, Wt1, bt1, Wt2, bt2, Wa1, ba1, Wa2, ba2, S);
    }
}

// ---------------------------------------------------------------------------
// K4: out[row][s] = w0*r0[s] + w1*r1[s]; resets flags for graph replay.
// ---------------------------------------------------------------------------
__global__ void k4_bcast(float* __restrict__ out, int S) {
    if (blockIdx.x == 0 && threadIdx.x == 0) {
        g_flagA = 0; g_flagB = 0; g_flagC = 0; g_rowctr = 0;
    }
    __shared__ float wsh[2];
    if (threadIdx.x < 2) wsh[threadIdx.x] = g_w[threadIdx.x];
    __syncthreads();
    float w0 = wsh[0], w1 = wsh[1];
    int row = blockIdx.x;
    const float4* r04 = (const float4*)g_r0;
    const float4* r14 = (const float4*)g_r1;
    float4* o4 = (float4*)(out + (size_t)row * S);
    int n4 = S >> 2;
    for (int c = threadIdx.x; c < n4; c += blockDim.x) {
        float4 a = __ldg(r04 + c);
        float4 b = __ldg(r14 + c);
        float4 v;
        v.x = fmaf(w0, a.x, w1 * b.x);
        v.y = fmaf(w0, a.y, w1 * b.y);
        v.z = fmaf(w0, a.z, w1 * b.z);
        v.w = fmaf(w0, a.w, w1 * b.w);
        __stcs(o4 + c, v);
    }
}

// ---------------------------------------------------------------------------
extern "C" void kernel_launch(void* const* d_in, const int* in_sizes, int n_in,
                              void* d_out, int out_size) {
    const float* query = (const float*)d_in[0];
    const float* key   = (const float*)d_in[1];
    const float* dg    = (const float*)d_in[2];
    const float* ts    = (const float*)d_in[3];
    const float* Wt1   = (const float*)d_in[4];
    const float* bt1   = (const float*)d_in[5];
    const float* Wt2   = (const float*)d_in[6];
    const float* bt2   = (const float*)d_in[7];
    const float* Wa1   = (const float*)d_in[8];
    const float* ba1   = (const float*)d_in[9];
    const float* Wa2   = (const float*)d_in[10];
    const float* ba2   = (const float*)d_in[11];
    const float* Wg    = (const float*)d_in[12];
    const float* bg    = (const float*)d_in[13];

    int S = in_sizes[1] / H;

    kPre<<<G, 256>>>((const float4*)query, (const float4*)key,
                     ts, dg, Wt1, bt1, Wt2, bt2,
                     Wa1, ba1, Wa2, ba2, Wg, bg, S);
    k4_bcast<<<S, 256>>>((float*)d_out, S);
}